// round 14
// baseline (speedup 1.0000x reference)
#include <cuda_runtime.h>
#include <cuda_fp16.h>
#include <cstdint>
#include <cstddef>

#define NROWS 8192
#define DDIM  512
#define BM 128
#define BN 128
#define NKC 8                 // 8 chunks of K=64 fp16 (128 B per row-chunk)

// ---------------- device scratch (allowed: __device__ globals) ----------------
__device__ __align__(16) __half g_xh [(size_t)NROWS * DDIM];
__device__ __align__(16) __half g_x1h[(size_t)NROWS * DDIM];
__device__ float g_xsq [NROWS];
__device__ float g_x1sq[NROWS];

// ---------------- PTX helpers (sm_80-era, compile under compute_103) ----------
__device__ __forceinline__ uint32_t smem_u32(const void* p) {
    uint32_t a;
    asm("{ .reg .u64 t; cvta.to.shared.u64 t, %1; cvt.u32.u64 %0, t; }" : "=r"(a) : "l"(p));
    return a;
}
__device__ __forceinline__ void cp_async16(uint32_t s, const void* g) {
    asm volatile("cp.async.cg.shared.global [%0], [%1], 16;" :: "r"(s), "l"(g));
}
#define CP_COMMIT()   asm volatile("cp.async.commit_group;" ::: "memory")
#define CP_WAIT(N)    asm volatile("cp.async.wait_group %0;" :: "n"(N) : "memory")

#define LDMX4(r, addr) \
    asm volatile("ldmatrix.sync.aligned.m8n8.x4.shared.b16 {%0,%1,%2,%3}, [%4];" \
                 : "=r"((r)[0]), "=r"((r)[1]), "=r"((r)[2]), "=r"((r)[3]) : "r"(addr))

// fp16 in, fp16 accumulate: D,C are 2 x f16x2 regs
#define MMAH16(c, a, b) \
    asm volatile("mma.sync.aligned.m16n8k16.row.col.f16.f16.f16.f16 " \
                 "{%0,%1}, {%2,%3,%4,%5}, {%6,%7}, {%0,%1};" \
                 : "+r"((c)[0]), "+r"((c)[1]) \
                 : "r"((a)[0]), "r"((a)[1]), "r"((a)[2]), "r"((a)[3]), \
                   "r"((b)[0]), "r"((b)[1]))

__device__ __forceinline__ uint32_t sw128(uint32_t off) {
    return off ^ ((off >> 3) & 0x70);
}

// SMEM layout (dynamic): stage0[A16K B16K] stage1[A16K B16K]
#define SM_STAGE  32768
#define SM_TOTAL  65536

// ---------------- kernel 1: fp32 -> fp16 convert + row norms ----------------
__global__ void __launch_bounds__(128)
prep_kernel(const float* __restrict__ x, const float* __restrict__ x1) {
    const int row = blockIdx.x;
    const float* src = blockIdx.y ? x1 : x;
    __half* dst = blockIdx.y ? g_x1h : g_xh;
    float* nrm = blockIdx.y ? g_x1sq : g_xsq;
    const int tid = threadIdx.x, lane = tid & 31, wid = tid >> 5;

    float4 v = reinterpret_cast<const float4*>(src + (size_t)row * DDIM)[tid];
    float s = v.x * v.x + v.y * v.y + v.z * v.z + v.w * v.w;

    __half2* d2 = reinterpret_cast<__half2*>(dst + (size_t)row * DDIM);
    d2[tid * 2 + 0] = __floats2half2_rn(v.x, v.y);
    d2[tid * 2 + 1] = __floats2half2_rn(v.z, v.w);

    #pragma unroll
    for (int o = 16; o; o >>= 1) s += __shfl_xor_sync(0xFFFFFFFFu, s, o);
    __shared__ float ws[4];
    if (lane == 0) ws[wid] = s;
    __syncthreads();
    if (tid == 0) nrm[row] = ws[0] + ws[1] + ws[2] + ws[3];
}

// ---------------- kernel 2: HMMA fp16 GEMM + RBF epilogue ----------------
// 128 threads, 4 warps (2x2 grid, 64x64 warp tile), 3 CTAs/SM, 2-stage ring.
// ONE barrier per chunk: wait -> sync (publish + WAR protect) -> refill -> compute.
__global__ void __launch_bounds__(128, 3)
rbf_gemm_kernel(float* __restrict__ out) {
    extern __shared__ char smem[];
    const uint32_t sb = smem_u32(smem);
    const int tid = threadIdx.x, wid = tid >> 5, lane = tid & 31;
    const int warp_m = wid >> 1, warp_n = wid & 1;        // 2 x 2 warp grid
    const int m0 = blockIdx.y * BM, n0 = blockIdx.x * BN;

    const char* Ag = reinterpret_cast<const char*>(g_xh  + (size_t)m0 * DDIM);
    const char* Bg = reinterpret_cast<const char*>(g_x1h + (size_t)n0 * DDIM);

    // ---- prefetch addressing, folded: per-thread smem base + i*2048, gmem +i*16384
    const uint32_t pr_r0 = tid >> 3, pr_ch = tid & 7;
    const uint32_t pr_sw = sw128(pr_r0 * 128 + pr_ch * 16);   // invariant in i
    const size_t   pr_g0 = (size_t)pr_r0 * (DDIM * 2) + pr_ch * 16;

    auto prefetch = [&](int kc, uint32_t buf) {
        const uint32_t sa  = sb + buf * SM_STAGE + pr_sw;
        const uint32_t sbb = sa + 16384;
        const char* ga = Ag + pr_g0 + kc * 128;
        const char* gb = Bg + pr_g0 + kc * 128;
        #pragma unroll
        for (int i = 0; i < 8; i++) {
            cp_async16(sa  + i * 2048, ga + (size_t)i * 16384);
            cp_async16(sbb + i * 2048, gb + (size_t)i * 16384);
        }
        CP_COMMIT();
    };

    // ---- ldmatrix base addresses (per-thread constants; XOR in (ks<<5) per step)
    uint32_t abase[4], bbase[4];
    {
        const uint32_t hi = (lane >> 4) << 4;
        #pragma unroll
        for (int mt = 0; mt < 4; mt++) {
            const uint32_t m = warp_m * 64 + mt * 16 + (lane & 15);
            abase[mt] = m * 128 + (hi ^ ((m & 7) << 4));
        }
        const uint32_t g = lane >> 3, r = lane & 7, g1 = (g & 1) << 4;
        #pragma unroll
        for (int np = 0; np < 4; np++) {
            const uint32_t n = warp_n * 64 + (np * 2 + (g >> 1)) * 8 + r;
            bbase[np] = n * 128 + (g1 ^ ((n & 7) << 4));
        }
    }

    uint32_t c[4][8][2];                              // f16x2 accumulators
    #pragma unroll
    for (int mt = 0; mt < 4; mt++)
        #pragma unroll
        for (int nt = 0; nt < 8; nt++)
            c[mt][nt][0] = c[mt][nt][1] = 0u;

    prefetch(0, 0);
    uint32_t buf = 0;

    #pragma unroll
    for (int kc = 0; kc < NKC; kc++) {
        CP_WAIT(0);               // only group in flight is chunk kc
        __syncthreads();          // publish chunk kc; all warps past compute kc-1
        if (kc + 1 < NKC)
            prefetch(kc + 1, buf ^ 1);   // safe: buf^1's readers all passed the sync

        const uint32_t sa  = sb + buf * SM_STAGE;
        const uint32_t sbb = sa + 16384;

        #pragma unroll
        for (int ks = 0; ks < 4; ks++) {                 // 4 x K=16 per chunk
            const uint32_t kx = ks << 5;
            uint32_t a[4][4], b[8][2];
            #pragma unroll
            for (int mt = 0; mt < 4; mt++)
                LDMX4(a[mt], sa + (abase[mt] ^ kx));
            #pragma unroll
            for (int np = 0; np < 4; np++) {
                uint32_t t[4];
                LDMX4(t, sbb + (bbase[np] ^ kx));
                b[np * 2][0] = t[0]; b[np * 2][1] = t[1];
                b[np * 2 + 1][0] = t[2]; b[np * 2 + 1][1] = t[3];
            }
            #pragma unroll
            for (int mt = 0; mt < 4; mt++)
                #pragma unroll
                for (int nt = 0; nt < 8; nt++)
                    MMAH16(c[mt][nt], a[mt], b[nt]);
        }
        buf ^= 1;
    }

    // ---- epilogue: d = |x|^2 + |x1|^2 - 2*cross ; out = exp(-max(d, 0)) ----
    const int lr = lane >> 2, lc = (lane & 3) * 2;
    const float* __restrict__ xsq  = g_xsq;
    const float* __restrict__ x1sq = g_x1sq;

    float a0s[8], a1s[8];
    #pragma unroll
    for (int nt = 0; nt < 8; nt++) {
        const int nc = warp_n * 64 + nt * 8 + lc;
        a0s[nt] = __ldg(x1sq + n0 + nc);
        a1s[nt] = __ldg(x1sq + n0 + nc + 1);
    }

    #pragma unroll
    for (int mt = 0; mt < 4; mt++) {
        const int ml = warp_m * 64 + mt * 16 + lr;       // frag rows ml, ml+8
        const float xs0 = __ldg(xsq + m0 + ml);
        const float xs1 = __ldg(xsq + m0 + ml + 8);
        float* o0 = out + (size_t)(m0 + ml) * NROWS + n0;
        float* o1 = o0 + (size_t)8 * NROWS;
        #pragma unroll
        for (int nt = 0; nt < 8; nt++) {
            const int nc = warp_n * 64 + nt * 8 + lc;
            const float2 f0 = __half22float2(*reinterpret_cast<__half2*>(&c[mt][nt][0]));
            const float2 f1 = __half22float2(*reinterpret_cast<__half2*>(&c[mt][nt][1]));
            float2 v0, v1;
            v0.x = __expf(-fmaxf(xs0 + a0s[nt] - 2.0f * f0.x, 0.0f));
            v0.y = __expf(-fmaxf(xs0 + a1s[nt] - 2.0f * f0.y, 0.0f));
            v1.x = __expf(-fmaxf(xs1 + a0s[nt] - 2.0f * f1.x, 0.0f));
            v1.y = __expf(-fmaxf(xs1 + a1s[nt] - 2.0f * f1.y, 0.0f));
            *reinterpret_cast<float2*>(o0 + nc) = v0;
            *reinterpret_cast<float2*>(o1 + nc) = v1;
        }
    }
}

// ---------------- launch ----------------
extern "C" void kernel_launch(void* const* d_in, const int* in_sizes, int n_in,
                              void* d_out, int out_size) {
    const float* x  = (const float*)d_in[0];
    const float* x1 = (const float*)d_in[1];
    float* out = (float*)d_out;

    cudaFuncSetAttribute(rbf_gemm_kernel,
                         cudaFuncAttributeMaxDynamicSharedMemorySize, SM_TOTAL);

    prep_kernel<<<dim3(NROWS, 2), 128>>>(x, x1);
    rbf_gemm_kernel<<<dim3(NROWS / BN, NROWS / BM), 128, SM_TOTAL>>>(out);
}

// round 15
// speedup vs baseline: 1.5233x; 1.5233x over previous
#include <cuda_runtime.h>
#include <cuda_fp16.h>
#include <cstdint>
#include <cstddef>

#define NROWS 8192
#define DDIM  512
#define BM 128
#define BN 128
#define NKC 8                 // 8 chunks of K=64 fp16 (128 B per row-chunk)

// ---------------- device scratch (allowed: __device__ globals) ----------------
__device__ __align__(16) __half g_xh [(size_t)NROWS * DDIM];
__device__ __align__(16) __half g_x1h[(size_t)NROWS * DDIM];
__device__ float g_xsq [NROWS];
__device__ float g_x1sq[NROWS];

// ---------------- PTX helpers (sm_80-era, compile under compute_103) ----------
__device__ __forceinline__ uint32_t smem_u32(const void* p) {
    uint32_t a;
    asm("{ .reg .u64 t; cvta.to.shared.u64 t, %1; cvt.u32.u64 %0, t; }" : "=r"(a) : "l"(p));
    return a;
}
__device__ __forceinline__ void cp_async16(uint32_t s, const void* g) {
    asm volatile("cp.async.cg.shared.global [%0], [%1], 16;" :: "r"(s), "l"(g));
}
#define CP_COMMIT()   asm volatile("cp.async.commit_group;" ::: "memory")
#define CP_WAIT(N)    asm volatile("cp.async.wait_group %0;" :: "n"(N) : "memory")

#define LDMX4(r, addr) \
    asm volatile("ldmatrix.sync.aligned.m8n8.x4.shared.b16 {%0,%1,%2,%3}, [%4];" \
                 : "=r"((r)[0]), "=r"((r)[1]), "=r"((r)[2]), "=r"((r)[3]) : "r"(addr))

// fp16 in, fp16 accumulate: D,C are 2 x f16x2 regs
#define MMAH16(c, a, b) \
    asm volatile("mma.sync.aligned.m16n8k16.row.col.f16.f16.f16.f16 " \
                 "{%0,%1}, {%2,%3,%4,%5}, {%6,%7}, {%0,%1};" \
                 : "+r"((c)[0]), "+r"((c)[1]) \
                 : "r"((a)[0]), "r"((a)[1]), "r"((a)[2]), "r"((a)[3]), \
                   "r"((b)[0]), "r"((b)[1]))

__device__ __forceinline__ uint32_t sw128(uint32_t off) {
    return off ^ ((off >> 3) & 0x70);
}

// SMEM layout (dynamic): stage0[A16K B16K] stage1[A16K B16K]
#define SM_STAGE  32768
#define SM_TOTAL  65536

// ---------------- kernel 1: fp32 -> fp16 convert + row norms ----------------
// One warp per row, 8 rows per block, pure shuffle reduction (no smem/syncs).
__global__ void __launch_bounds__(256)
prep_kernel(const float* __restrict__ x, const float* __restrict__ x1) {
    const int wz = threadIdx.x >> 5, lane = threadIdx.x & 31;
    const int row = blockIdx.x * 8 + wz;
    const float* src = blockIdx.y ? x1 : x;
    __half* dst = blockIdx.y ? g_x1h : g_xh;
    float* nrm = blockIdx.y ? g_x1sq : g_xsq;

    const float4* s4 = reinterpret_cast<const float4*>(src + (size_t)row * DDIM);
    __half2* d2 = reinterpret_cast<__half2*>(dst + (size_t)row * DDIM);

    float s = 0.0f;
    #pragma unroll
    for (int i = 0; i < 4; i++) {
        const int idx = lane + i * 32;          // 128 float4 per row
        float4 v = s4[idx];
        s += v.x * v.x + v.y * v.y + v.z * v.z + v.w * v.w;
        d2[idx * 2 + 0] = __floats2half2_rn(v.x, v.y);
        d2[idx * 2 + 1] = __floats2half2_rn(v.z, v.w);
    }
    #pragma unroll
    for (int o = 16; o; o >>= 1) s += __shfl_xor_sync(0xFFFFFFFFu, s, o);
    if (lane == 0) nrm[row] = s;
}

// ---------------- kernel 2: HMMA fp16 GEMM + RBF epilogue ----------------
// 128 threads, 4 warps (2x2 grid, 64x64 warp tile), 3 CTAs/SM, 2-stage ring.
// R13 ordering (proven): prefetch(kc+1) BEFORE wait -> sync -> compute -> sync.
__global__ void __launch_bounds__(128, 3)
rbf_gemm_kernel(float* __restrict__ out) {
    extern __shared__ char smem[];
    const uint32_t sb = smem_u32(smem);
    const int tid = threadIdx.x, wid = tid >> 5, lane = tid & 31;
    const int warp_m = wid >> 1, warp_n = wid & 1;        // 2 x 2 warp grid
    const int m0 = blockIdx.y * BM, n0 = blockIdx.x * BN;

    const char* Ag = reinterpret_cast<const char*>(g_xh  + (size_t)m0 * DDIM);
    const char* Bg = reinterpret_cast<const char*>(g_x1h + (size_t)n0 * DDIM);

    // ---- prefetch addressing, folded: per-thread smem base + i*2048, gmem +i*16384
    const uint32_t pr_r0 = tid >> 3, pr_ch = tid & 7;
    const uint32_t pr_sw = sw128(pr_r0 * 128 + pr_ch * 16);   // invariant in i
    const size_t   pr_g0 = (size_t)pr_r0 * (DDIM * 2) + pr_ch * 16;

    auto prefetch = [&](int kc, uint32_t buf) {
        const uint32_t sa  = sb + buf * SM_STAGE + pr_sw;
        const uint32_t sbb = sa + 16384;
        const char* ga = Ag + pr_g0 + kc * 128;
        const char* gb = Bg + pr_g0 + kc * 128;
        #pragma unroll
        for (int i = 0; i < 8; i++) {
            cp_async16(sa  + i * 2048, ga + (size_t)i * 16384);
            cp_async16(sbb + i * 2048, gb + (size_t)i * 16384);
        }
        CP_COMMIT();
    };

    // ---- ldmatrix base addresses (per-thread constants; XOR in (ks<<5) per step)
    uint32_t abase[4], bbase[4];
    {
        const uint32_t hi = (lane >> 4) << 4;
        #pragma unroll
        for (int mt = 0; mt < 4; mt++) {
            const uint32_t m = warp_m * 64 + mt * 16 + (lane & 15);
            abase[mt] = m * 128 + (hi ^ ((m & 7) << 4));
        }
        const uint32_t g = lane >> 3, r = lane & 7, g1 = (g & 1) << 4;
        #pragma unroll
        for (int np = 0; np < 4; np++) {
            const uint32_t n = warp_n * 64 + (np * 2 + (g >> 1)) * 8 + r;
            bbase[np] = n * 128 + (g1 ^ ((n & 7) << 4));
        }
    }

    uint32_t c[4][8][2];                              // f16x2 accumulators
    #pragma unroll
    for (int mt = 0; mt < 4; mt++)
        #pragma unroll
        for (int nt = 0; nt < 8; nt++)
            c[mt][nt][0] = c[mt][nt][1] = 0u;

    prefetch(0, 0);
    uint32_t buf = 0;

    #pragma unroll
    for (int kc = 0; kc < NKC; kc++) {
        if (kc + 1 < NKC) { prefetch(kc + 1, buf ^ 1); CP_WAIT(1); }
        else              { CP_WAIT(0); }
        __syncthreads();

        const uint32_t sa  = sb + buf * SM_STAGE;
        const uint32_t sbb = sa + 16384;

        #pragma unroll
        for (int ks = 0; ks < 4; ks++) {                 // 4 x K=16 per chunk
            const uint32_t kx = ks << 5;
            uint32_t a[4][4], b[8][2];
            #pragma unroll
            for (int mt = 0; mt < 4; mt++)
                LDMX4(a[mt], sa + (abase[mt] ^ kx));
            #pragma unroll
            for (int np = 0; np < 4; np++) {
                uint32_t t[4];
                LDMX4(t, sbb + (bbase[np] ^ kx));
                b[np * 2][0] = t[0]; b[np * 2][1] = t[1];
                b[np * 2 + 1][0] = t[2]; b[np * 2 + 1][1] = t[3];
            }
            #pragma unroll
            for (int mt = 0; mt < 4; mt++)
                #pragma unroll
                for (int nt = 0; nt < 8; nt++)
                    MMAH16(c[mt][nt], a[mt], b[nt]);
        }
        if (kc + 1 < NKC) __syncthreads();   // protect buf before next refill
        buf ^= 1;
    }

    // ---- epilogue: d = |x|^2 + |x1|^2 - 2*cross ; out = exp(-max(d, 0)) ----
    const int lr = lane >> 2, lc = (lane & 3) * 2;
    const float* __restrict__ xsq  = g_xsq;
    const float* __restrict__ x1sq = g_x1sq;

    float a0s[8], a1s[8];
    #pragma unroll
    for (int nt = 0; nt < 8; nt++) {
        const int nc = warp_n * 64 + nt * 8 + lc;
        a0s[nt] = __ldg(x1sq + n0 + nc);
        a1s[nt] = __ldg(x1sq + n0 + nc + 1);
    }

    #pragma unroll
    for (int mt = 0; mt < 4; mt++) {
        const int ml = warp_m * 64 + mt * 16 + lr;       // frag rows ml, ml+8
        const float xs0 = __ldg(xsq + m0 + ml);
        const float xs1 = __ldg(xsq + m0 + ml + 8);
        float* o0 = out + (size_t)(m0 + ml) * NROWS + n0;
        float* o1 = o0 + (size_t)8 * NROWS;
        #pragma unroll
        for (int nt = 0; nt < 8; nt++) {
            const int nc = warp_n * 64 + nt * 8 + lc;
            const float2 f0 = __half22float2(*reinterpret_cast<__half2*>(&c[mt][nt][0]));
            const float2 f1 = __half22float2(*reinterpret_cast<__half2*>(&c[mt][nt][1]));
            float2 v0, v1;
            v0.x = __expf(-fmaxf(xs0 + a0s[nt] - 2.0f * f0.x, 0.0f));
            v0.y = __expf(-fmaxf(xs0 + a1s[nt] - 2.0f * f0.y, 0.0f));
            v1.x = __expf(-fmaxf(xs1 + a0s[nt] - 2.0f * f1.x, 0.0f));
            v1.y = __expf(-fmaxf(xs1 + a1s[nt] - 2.0f * f1.y, 0.0f));
            *reinterpret_cast<float2*>(o0 + nc) = v0;
            *reinterpret_cast<float2*>(o1 + nc) = v1;
        }
    }
}

// ---------------- launch ----------------
extern "C" void kernel_launch(void* const* d_in, const int* in_sizes, int n_in,
                              void* d_out, int out_size) {
    const float* x  = (const float*)d_in[0];
    const float* x1 = (const float*)d_in[1];
    float* out = (float*)d_out;

    cudaFuncSetAttribute(rbf_gemm_kernel,
                         cudaFuncAttributeMaxDynamicSharedMemorySize, SM_TOTAL);

    prep_kernel<<<dim3(NROWS / 8, 2), 256>>>(x, x1);
    rbf_gemm_kernel<<<dim3(NROWS / BN, NROWS / BM), 128, SM_TOTAL>>>(out);
}